// round 4
// baseline (speedup 1.0000x reference)
#include <cuda_runtime.h>
#include <cstdint>

#define KDIM 7168
#define ODIM 16384
#define MDIM 32
#define OTILE 128
#define KTILE 128
#define NKT (KDIM / KTILE)     /* 56 */
#define NTHREADS 512           /* 16 warps: warps 0-7 = ks 0-7, warps 8-15 = ks 8-15 */
#define WS_STRIDE 132          /* 128 + 4 pad floats -> conflict-free fragment LDS */
#define W_STAGE (128 * WS_STRIDE)          /* floats per W stage: 16896 */
#define NSTAGE 3
#define XS_STRIDE 132

// dynamic smem: [ W stages: 3 * 16896 floats ][ xs: 32 * 132 u32 ]  = 219,648 B
#define SMEM_FLOATS (NSTAGE * W_STAGE + MDIM * XS_STRIDE)

__device__ __forceinline__ uint32_t smem_u32(const void* p) {
    uint32_t a;
    asm("{ .reg .u64 t; cvta.to.shared.u64 t, %1; cvt.u32.u64 %0, t; }" : "=r"(a) : "l"(p));
    return a;
}

__device__ __forceinline__ uint32_t tf32r(float v) {   // fp32 -> tf32 round-to-nearest
    uint32_t u;
    asm("cvt.rna.tf32.f32 %0, %1;" : "=r"(u) : "f"(v));
    return u;
}

__device__ __forceinline__ void cp_async16(uint32_t dst_smem, const void* src) {
    asm volatile("cp.async.cg.shared.global [%0], [%1], 16;" :: "r"(dst_smem), "l"(src) : "memory");
}
#define CP_COMMIT() asm volatile("cp.async.commit_group;" ::: "memory")
#define CP_WAIT2()  asm volatile("cp.async.wait_group 2;" ::: "memory")

__global__ __launch_bounds__(NTHREADS, 1)
void linear_tf32_mma(const float* __restrict__ X, const float* __restrict__ W,
                     const float* __restrict__ S, float* __restrict__ out)
{
    extern __shared__ float smem[];
    float*    wbuf = smem;
    uint32_t* xs   = reinterpret_cast<uint32_t*>(smem + NSTAGE * W_STAGE);

    const int tid  = threadIdx.x;
    const int lane = tid & 31;
    const int w    = tid >> 5;          // 0..15
    const int h    = w >> 3;            // ks-half: 0 -> ks 0-7, 1 -> ks 8-15
    const int wrow = w & 7;             // row-warp: owns o rows [wrow*16, wrow*16+16)
    const int bx   = blockIdx.x;
    const int o_base = bx * OTILE;

    const int g = lane >> 2;   // 0..7
    const int c = lane & 3;    // 0..3

    float acc[4][4];
    #pragma unroll
    for (int i = 0; i < 4; i++)
        #pragma unroll
        for (int j = 0; j < 4; j++) acc[i][j] = 0.0f;

    // ---- prologue: x tile kt=0 into registers, W stages 0..2 via cp.async ----
    float4 xr[2];   // 4096 floats / 512 threads = 8 floats
    #pragma unroll
    for (int i = 0; i < 2; i++) {
        int idx = i * NTHREADS + tid;
        int m = idx >> 5, c4 = idx & 31;
        xr[i] = *reinterpret_cast<const float4*>(X + (size_t)m * KDIM + (size_t)c4 * 4);
    }

    const int cprow0 = tid >> 5;        // + 16*i
    const int cpc4   = tid & 31;

    #pragma unroll
    for (int st = 0; st < NSTAGE; st++) {
        const uint32_t dbase = smem_u32(wbuf + st * W_STAGE);
        const float*   gsrc  = W + (size_t)o_base * KDIM + (size_t)st * KTILE;
        #pragma unroll
        for (int i = 0; i < 8; i++) {
            int row = cprow0 + i * 16;
            cp_async16(dbase + (uint32_t)(row * WS_STRIDE + cpc4 * 4) * 4u,
                       gsrc + (size_t)row * KDIM + (size_t)cpc4 * 4);
        }
        CP_COMMIT();
    }

    #pragma unroll 1
    for (int kt = 0; kt < NKT; kt++) {
        const float s = S[(size_t)bx * NKT + kt];

        // scaled + tf32-rounded x tile -> smem
        #pragma unroll
        for (int i = 0; i < 2; i++) {
            int idx = i * NTHREADS + tid;
            int m = idx >> 5, c4 = idx & 31;
            uint32_t* p = &xs[m * XS_STRIDE + c4 * 4];
            p[0] = tf32r(xr[i].x * s);
            p[1] = tf32r(xr[i].y * s);
            p[2] = tf32r(xr[i].z * s);
            p[3] = tf32r(xr[i].w * s);
        }

        CP_WAIT2();            // W stage kt resident
        __syncthreads();       // xs + W visible to all warps

        // prefetch next x tile (L2-resident, hidden under MMA)
        if (kt + 1 < NKT) {
            #pragma unroll
            for (int i = 0; i < 2; i++) {
                int idx = i * NTHREADS + tid;
                int m = idx >> 5, c4 = idx & 31;
                xr[i] = *reinterpret_cast<const float4*>(
                    X + (size_t)m * KDIM + (size_t)(kt + 1) * KTILE + (size_t)c4 * 4);
            }
        }

        const float* wstage = wbuf + (kt % NSTAGE) * W_STAGE;
        const int r0 = wrow * 16 + g;

        #pragma unroll
        for (int ks = 0; ks < 8; ks++) {
            const int k0 = h * 64 + ks * 8;     // this warp's ks-half
            uint32_t a0 = tf32r(wstage[ r0      * WS_STRIDE + k0 + c    ]);
            uint32_t a1 = tf32r(wstage[(r0 + 8) * WS_STRIDE + k0 + c    ]);
            uint32_t a2 = tf32r(wstage[ r0      * WS_STRIDE + k0 + c + 4]);
            uint32_t a3 = tf32r(wstage[(r0 + 8) * WS_STRIDE + k0 + c + 4]);

            #pragma unroll
            for (int mt = 0; mt < 4; mt++) {
                uint32_t b0 = xs[(mt * 8 + g) * XS_STRIDE + k0 + c];
                uint32_t b1 = xs[(mt * 8 + g) * XS_STRIDE + k0 + 4 + c];
                asm volatile(
                    "mma.sync.aligned.m16n8k8.row.col.f32.tf32.tf32.f32 "
                    "{%0,%1,%2,%3}, {%4,%5,%6,%7}, {%8,%9}, {%0,%1,%2,%3};"
                    : "+f"(acc[mt][0]), "+f"(acc[mt][1]),
                      "+f"(acc[mt][2]), "+f"(acc[mt][3])
                    : "r"(a0), "r"(a1), "r"(a2), "r"(a3), "r"(b0), "r"(b1));
            }
        }

        __syncthreads();       // all warps done reading wstage + xs

        // refill this stage's buffer with tile kt+NSTAGE (or commit empty group)
        if (kt + NSTAGE < NKT) {
            const uint32_t dbase = smem_u32(wbuf + (kt % NSTAGE) * W_STAGE);
            const float*   gsrc  = W + (size_t)o_base * KDIM + (size_t)(kt + NSTAGE) * KTILE;
            #pragma unroll
            for (int i = 0; i < 8; i++) {
                int row = cprow0 + i * 16;
                cp_async16(dbase + (uint32_t)(row * WS_STRIDE + cpc4 * 4) * 4u,
                           gsrc + (size_t)row * KDIM + (size_t)cpc4 * 4);
            }
        }
        CP_COMMIT();
    }

    // ---- epilogue: reduce the two ks-halves, then store ----
    // group 1 dumps fragments to smem (reuse W buffer region), group 0 adds.
    float4* red = reinterpret_cast<float4*>(wbuf);   // 4 * 256 float4 = 16 KB
    if (h == 1) {
        #pragma unroll
        for (int mt = 0; mt < 4; mt++)
            red[mt * 256 + wrow * 32 + lane] =
                make_float4(acc[mt][0], acc[mt][1], acc[mt][2], acc[mt][3]);
    }
    __syncthreads();

    if (h == 0) {
        const int o0 = o_base + wrow * 16 + g;
        #pragma unroll
        for (int mt = 0; mt < 4; mt++) {
            float4 v = red[mt * 256 + wrow * 32 + lane];
            const int m0 = mt * 8 + c * 2;
            // d0:(g,2c) d1:(g,2c+1) d2:(g+8,2c) d3:(g+8,2c+1); rows=o, cols=m
            out[(size_t)m0       * ODIM + o0    ] = acc[mt][0] + v.x;
            out[(size_t)(m0 + 1) * ODIM + o0    ] = acc[mt][1] + v.y;
            out[(size_t)m0       * ODIM + o0 + 8] = acc[mt][2] + v.z;
            out[(size_t)(m0 + 1) * ODIM + o0 + 8] = acc[mt][3] + v.w;
        }
    }
}

extern "C" void kernel_launch(void* const* d_in, const int* in_sizes, int n_in,
                              void* d_out, int out_size) {
    const float* x = (const float*)d_in[0];
    const float* w = (const float*)d_in[1];
    const float* s = (const float*)d_in[2];
    float* out = (float*)d_out;

    const size_t smem_bytes = SMEM_FLOATS * sizeof(float);
    cudaFuncSetAttribute(linear_tf32_mma,
                         cudaFuncAttributeMaxDynamicSharedMemorySize, (int)smem_bytes);
    linear_tf32_mma<<<ODIM / OTILE, NTHREADS, smem_bytes>>>(x, w, s, out);
}

// round 5
// speedup vs baseline: 1.0272x; 1.0272x over previous
#include <cuda_runtime.h>
#include <cstdint>

#define KDIM 7168
#define ODIM 16384
#define MDIM 32
#define OTILE 128
#define KTILE 128
#define NKT (KDIM / KTILE)     /* 56 */
#define NTHREADS 512           /* 16 warps = 4 ks-quarters x 4 row-warps */
#define WS_STRIDE 132          /* 128 + 4 pad floats -> conflict-free fragment LDS */
#define W_STAGE (128 * WS_STRIDE)          /* floats per W stage: 16896 */
#define NSTAGE 3
#define XS_STRIDE 132

// dynamic smem: [ W stages: 3 * 16896 floats ][ xs: 32 * 132 u32 ]  = 219,648 B
#define SMEM_FLOATS (NSTAGE * W_STAGE + MDIM * XS_STRIDE)

__device__ __forceinline__ uint32_t smem_u32(const void* p) {
    uint32_t a;
    asm("{ .reg .u64 t; cvta.to.shared.u64 t, %1; cvt.u32.u64 %0, t; }" : "=r"(a) : "l"(p));
    return a;
}

__device__ __forceinline__ uint32_t tf32r(float v) {   // fp32 -> tf32 round-to-nearest
    uint32_t u;
    asm("cvt.rna.tf32.f32 %0, %1;" : "=r"(u) : "f"(v));
    return u;
}

__device__ __forceinline__ void cp_async16(uint32_t dst_smem, const void* src) {
    asm volatile("cp.async.cg.shared.global [%0], [%1], 16;" :: "r"(dst_smem), "l"(src) : "memory");
}
#define CP_COMMIT() asm volatile("cp.async.commit_group;" ::: "memory")
#define CP_WAIT2()  asm volatile("cp.async.wait_group 2;" ::: "memory")
#define CP_WAIT0()  asm volatile("cp.async.wait_group 0;" ::: "memory")

#define MMA_TF32(acc, a0, a1, a2, a3, b0, b1)                                  \
    asm volatile(                                                              \
        "mma.sync.aligned.m16n8k8.row.col.f32.tf32.tf32.f32 "                  \
        "{%0,%1,%2,%3}, {%4,%5,%6,%7}, {%8,%9}, {%0,%1,%2,%3};"                \
        : "+f"((acc)[0]), "+f"((acc)[1]), "+f"((acc)[2]), "+f"((acc)[3])       \
        : "r"(a0), "r"(a1), "r"(a2), "r"(a3), "r"(b0), "r"(b1))

__global__ __launch_bounds__(NTHREADS, 1)
void linear_tf32_mma(const float* __restrict__ X, const float* __restrict__ W,
                     const float* __restrict__ S, float* __restrict__ out)
{
    extern __shared__ float smem[];
    float*    wbuf = smem;
    uint32_t* xs   = reinterpret_cast<uint32_t*>(smem + NSTAGE * W_STAGE);

    const int tid  = threadIdx.x;
    const int lane = tid & 31;
    const int w    = tid >> 5;          // 0..15
    const int q    = w >> 2;            // ks-quarter (0..3): owns ks [q*4, q*4+4) of 16
    const int wrow = w & 3;             // row-warp: owns o rows [wrow*32, wrow*32+32)
    const int bx   = blockIdx.x;
    const int o_base = bx * OTILE;

    const int g = lane >> 2;   // 0..7
    const int c = lane & 3;    // 0..3

    // acc[blk][mt][4]: blk = o-row block (0: rows wrow*32+g(+8), 1: +16), mt = m-tile
    float acc[2][4][4];
    #pragma unroll
    for (int b = 0; b < 2; b++)
        #pragma unroll
        for (int i = 0; i < 4; i++)
            #pragma unroll
            for (int j = 0; j < 4; j++) acc[b][i][j] = 0.0f;

    // ---- prologue: x tile kt=0 into registers, W stages 0..2 via cp.async ----
    float4 xr[2];   // 4096 floats / 512 threads = 8 floats
    #pragma unroll
    for (int i = 0; i < 2; i++) {
        int idx = i * NTHREADS + tid;
        int m = idx >> 5, c4 = idx & 31;
        xr[i] = *reinterpret_cast<const float4*>(X + (size_t)m * KDIM + (size_t)c4 * 4);
    }

    const int cprow0 = tid >> 5;        // + 16*i
    const int cpc4   = lane;

    #pragma unroll
    for (int st = 0; st < NSTAGE; st++) {
        const uint32_t dbase = smem_u32(wbuf + st * W_STAGE);
        const float*   gsrc  = W + (size_t)o_base * KDIM + (size_t)st * KTILE;
        #pragma unroll
        for (int i = 0; i < 8; i++) {
            int row = cprow0 + i * 16;
            cp_async16(dbase + (uint32_t)(row * WS_STRIDE + cpc4 * 4) * 4u,
                       gsrc + (size_t)row * KDIM + (size_t)cpc4 * 4);
        }
        CP_COMMIT();
    }

    #pragma unroll 1
    for (int kt = 0; kt < NKT; kt++) {
        const float s = S[(size_t)bx * NKT + kt];

        // scaled + tf32-rounded x tile -> smem
        #pragma unroll
        for (int i = 0; i < 2; i++) {
            int idx = i * NTHREADS + tid;
            int m = idx >> 5, c4 = idx & 31;
            uint32_t* p = &xs[m * XS_STRIDE + c4 * 4];
            p[0] = tf32r(xr[i].x * s);
            p[1] = tf32r(xr[i].y * s);
            p[2] = tf32r(xr[i].z * s);
            p[3] = tf32r(xr[i].w * s);
        }

        CP_WAIT2();            // W stage kt resident
        __syncthreads();       // xs + W visible to all warps

        // prefetch next x tile (L2-resident, hidden under MMA)
        if (kt + 1 < NKT) {
            #pragma unroll
            for (int i = 0; i < 2; i++) {
                int idx = i * NTHREADS + tid;
                int m = idx >> 5, c4 = idx & 31;
                xr[i] = *reinterpret_cast<const float4*>(
                    X + (size_t)m * KDIM + (size_t)(kt + 1) * KTILE + (size_t)c4 * 4);
            }
        }

        const float* wstage = wbuf + (kt % NSTAGE) * W_STAGE;
        const int r0 = wrow * 32 + g;       // block 0 rows: r0, r0+8; block 1: +16

        #pragma unroll
        for (int ks = 0; ks < 4; ks++) {
            const int k0 = q * 32 + ks * 8;     // this warp's ks-quarter

            // A fragments for both row blocks (W side, tf32-rounded post-LDS)
            uint32_t a[2][4];
            #pragma unroll
            for (int b = 0; b < 2; b++) {
                const int r = r0 + b * 16;
                a[b][0] = tf32r(wstage[ r      * WS_STRIDE + k0 + c    ]);
                a[b][1] = tf32r(wstage[(r + 8) * WS_STRIDE + k0 + c    ]);
                a[b][2] = tf32r(wstage[ r      * WS_STRIDE + k0 + c + 4]);
                a[b][3] = tf32r(wstage[(r + 8) * WS_STRIDE + k0 + c + 4]);
            }

            #pragma unroll
            for (int mt = 0; mt < 4; mt++) {
                uint32_t b0 = xs[(mt * 8 + g) * XS_STRIDE + k0 + c];
                uint32_t b1 = xs[(mt * 8 + g) * XS_STRIDE + k0 + 4 + c];
                MMA_TF32(acc[0][mt], a[0][0], a[0][1], a[0][2], a[0][3], b0, b1);
                MMA_TF32(acc[1][mt], a[1][0], a[1][1], a[1][2], a[1][3], b0, b1);
            }
        }

        __syncthreads();       // all warps done reading wstage + xs

        // refill this stage's buffer with tile kt+NSTAGE (or commit empty group)
        if (kt + NSTAGE < NKT) {
            const uint32_t dbase = smem_u32(wbuf + (kt % NSTAGE) * W_STAGE);
            const float*   gsrc  = W + (size_t)o_base * KDIM + (size_t)(kt + NSTAGE) * KTILE;
            #pragma unroll
            for (int i = 0; i < 8; i++) {
                int row = cprow0 + i * 16;
                cp_async16(dbase + (uint32_t)(row * WS_STRIDE + cpc4 * 4) * 4u,
                           gsrc + (size_t)row * KDIM + (size_t)cpc4 * 4);
            }
        }
        CP_COMMIT();
    }

    // ---- epilogue: reduce the 4 ks-quarters, then store ----
    CP_WAIT0();
    __syncthreads();                     // retire W buffer, reuse as reduction scratch
    // red[(q-1)][wrow][blk][mt][lane] as float4; 3*4*2*4*32*16B = 49,152 B
    float4* red = reinterpret_cast<float4*>(wbuf);
    if (q > 0) {
        #pragma unroll
        for (int b = 0; b < 2; b++)
            #pragma unroll
            for (int mt = 0; mt < 4; mt++)
                red[(((q - 1) * 4 + wrow) * 8 + b * 4 + mt) * 32 + lane] =
                    make_float4(acc[b][mt][0], acc[b][mt][1], acc[b][mt][2], acc[b][mt][3]);
    }
    __syncthreads();

    if (q == 0) {
        #pragma unroll
        for (int b = 0; b < 2; b++) {
            const int o0 = o_base + wrow * 32 + b * 16 + g;
            #pragma unroll
            for (int mt = 0; mt < 4; mt++) {
                float4 r = acc[b][mt][0] == acc[b][mt][0]  // keep order; just init from acc
                    ? make_float4(acc[b][mt][0], acc[b][mt][1], acc[b][mt][2], acc[b][mt][3])
                    : make_float4(0.f, 0.f, 0.f, 0.f);
                #pragma unroll
                for (int qq = 0; qq < 3; qq++) {
                    float4 v = red[((qq * 4 + wrow) * 8 + b * 4 + mt) * 32 + lane];
                    r.x += v.x; r.y += v.y; r.z += v.z; r.w += v.w;
                }
                const int m0 = mt * 8 + c * 2;
                // d0:(g,2c) d1:(g,2c+1) d2:(g+8,2c) d3:(g+8,2c+1); rows=o, cols=m
                out[(size_t)m0       * ODIM + o0    ] = r.x;
                out[(size_t)(m0 + 1) * ODIM + o0    ] = r.y;
                out[(size_t)m0       * ODIM + o0 + 8] = r.z;
                out[(size_t)(m0 + 1) * ODIM + o0 + 8] = r.w;
            }
        }
    }
}

extern "C" void kernel_launch(void* const* d_in, const int* in_sizes, int n_in,
                              void* d_out, int out_size) {
    const float* x = (const float*)d_in[0];
    const float* w = (const float*)d_in[1];
    const float* s = (const float*)d_in[2];
    float* out = (float*)d_out;

    const size_t smem_bytes = SMEM_FLOATS * sizeof(float);
    cudaFuncSetAttribute(linear_tf32_mma,
                         cudaFuncAttributeMaxDynamicSharedMemorySize, (int)smem_bytes);
    linear_tf32_mma<<<ODIM / OTILE, NTHREADS, smem_bytes>>>(x, w, s, out);
}

// round 7
// speedup vs baseline: 1.4810x; 1.4419x over previous
#include <cuda_runtime.h>
#include <cstdint>

#define KDIM 7168
#define ODIM 16384
#define MDIM 32
#define OTILE 64
#define KTILE 128
#define NKT (KDIM / KTILE)     /* 56 */
#define NTHREADS 256           /* 8 warps = 4 ks-quarters x 2 row-warps */
#define WS_STRIDE 132          /* 128 + 4 pad floats -> conflict-free fragment LDS */
#define W_STAGE (OTILE * WS_STRIDE)        /* floats per W stage: 8448 */
#define NSTAGE 2
#define XS_STRIDE 132

// dynamic smem: [ W stages: 2 * 8448 floats ][ xs: 32 * 132 u32 ] = 84,480 B -> 2 CTAs/SM
#define SMEM_FLOATS (NSTAGE * W_STAGE + MDIM * XS_STRIDE)

__device__ __forceinline__ uint32_t smem_u32(const void* p) {
    uint32_t a;
    asm("{ .reg .u64 t; cvta.to.shared.u64 t, %1; cvt.u32.u64 %0, t; }" : "=r"(a) : "l"(p));
    return a;
}

__device__ __forceinline__ uint32_t tf32r(float v) {   // fp32 -> tf32 round-to-nearest
    uint32_t u;
    asm("cvt.rna.tf32.f32 %0, %1;" : "=r"(u) : "f"(v));
    return u;
}

__device__ __forceinline__ void cp_async16(uint32_t dst_smem, const void* src) {
    asm volatile("cp.async.cg.shared.global [%0], [%1], 16;" :: "r"(dst_smem), "l"(src) : "memory");
}
#define CP_COMMIT() asm volatile("cp.async.commit_group;" ::: "memory")
#define CP_WAIT1()  asm volatile("cp.async.wait_group 1;" ::: "memory")
#define CP_WAIT0()  asm volatile("cp.async.wait_group 0;" ::: "memory")

#define MMA_TF32(acc, a0, a1, a2, a3, b0, b1)                                  \
    asm volatile(                                                              \
        "mma.sync.aligned.m16n8k8.row.col.f32.tf32.tf32.f32 "                  \
        "{%0,%1,%2,%3}, {%4,%5,%6,%7}, {%8,%9}, {%0,%1,%2,%3};"                \
        : "+f"((acc)[0]), "+f"((acc)[1]), "+f"((acc)[2]), "+f"((acc)[3])       \
        : "r"(a0), "r"(a1), "r"(a2), "r"(a3), "r"(b0), "r"(b1))

__global__ __launch_bounds__(NTHREADS, 2)
void linear_tf32_mma(const float* __restrict__ X, const float* __restrict__ W,
                     const float* __restrict__ S, float* __restrict__ out)
{
    extern __shared__ float smem[];
    float*    wbuf = smem;
    uint32_t* xs   = reinterpret_cast<uint32_t*>(smem + NSTAGE * W_STAGE);

    const int tid  = threadIdx.x;
    const int lane = tid & 31;
    const int w    = tid >> 5;          // 0..7
    const int q    = w >> 1;            // ks-quarter (0..3): owns ks [q*4, q*4+4) of 16
    const int wrow = w & 1;             // row-warp: owns o rows [wrow*32, wrow*32+32)
    const int bx   = blockIdx.x;
    const int o_base = bx * OTILE;
    // scale row: weight_scale_inv blocks are 128 o-rows; OTILE=64 -> two o-blocks per scale row
    const int srow = bx >> 1;

    const int g = lane >> 2;   // 0..7
    const int c = lane & 3;    // 0..3

    // acc[blk][mt][4]: blk = o-row block (rows wrow*32 + blk*16 + g(+8)), mt = m-tile
    float acc[2][4][4];
    #pragma unroll
    for (int b = 0; b < 2; b++)
        #pragma unroll
        for (int i = 0; i < 4; i++)
            #pragma unroll
            for (int j = 0; j < 4; j++) acc[b][i][j] = 0.0f;

    // ---- prologue: x tile kt=0 into registers, W stages 0..1 via cp.async ----
    float4 xr[4];   // 4096 floats / 256 threads = 16 floats
    #pragma unroll
    for (int i = 0; i < 4; i++) {
        int idx = i * NTHREADS + tid;
        int m = idx >> 5, c4 = idx & 31;
        xr[i] = *reinterpret_cast<const float4*>(X + (size_t)m * KDIM + (size_t)c4 * 4);
    }

    const int cprow0 = tid >> 5;        // + 8*i, i<8 -> rows 0..63
    const int cpc4   = lane;

    #pragma unroll
    for (int st = 0; st < NSTAGE; st++) {
        const uint32_t dbase = smem_u32(wbuf + st * W_STAGE);
        const float*   gsrc  = W + (size_t)o_base * KDIM + (size_t)st * KTILE;
        #pragma unroll
        for (int i = 0; i < 8; i++) {
            int row = cprow0 + i * 8;
            cp_async16(dbase + (uint32_t)(row * WS_STRIDE + cpc4 * 4) * 4u,
                       gsrc + (size_t)row * KDIM + (size_t)cpc4 * 4);
        }
        CP_COMMIT();
    }

    #pragma unroll 1
    for (int kt = 0; kt < NKT; kt++) {
        const float s = S[(size_t)srow * NKT + kt];

        // scaled + tf32-rounded x tile -> smem
        #pragma unroll
        for (int i = 0; i < 4; i++) {
            int idx = i * NTHREADS + tid;
            int m = idx >> 5, c4 = idx & 31;
            uint32_t* p = &xs[m * XS_STRIDE + c4 * 4];
            p[0] = tf32r(xr[i].x * s);
            p[1] = tf32r(xr[i].y * s);
            p[2] = tf32r(xr[i].z * s);
            p[3] = tf32r(xr[i].w * s);
        }

        CP_WAIT1();            // W stage kt resident (only kt+1 may remain pending)
        __syncthreads();       // xs + W visible to all warps

        // prefetch next x tile (L2-resident, hidden under MMA)
        if (kt + 1 < NKT) {
            #pragma unroll
            for (int i = 0; i < 4; i++) {
                int idx = i * NTHREADS + tid;
                int m = idx >> 5, c4 = idx & 31;
                xr[i] = *reinterpret_cast<const float4*>(
                    X + (size_t)m * KDIM + (size_t)(kt + 1) * KTILE + (size_t)c4 * 4);
            }
        }

        const float* wstage = wbuf + (kt & 1) * W_STAGE;
        const int r0 = wrow * 32 + g;       // block 0 rows: r0, r0+8; block 1: +16

        #pragma unroll
        for (int ks = 0; ks < 4; ks++) {
            const int k0 = q * 32 + ks * 8;     // this warp's ks-quarter

            uint32_t a[2][4];
            #pragma unroll
            for (int b = 0; b < 2; b++) {
                const int r = r0 + b * 16;
                a[b][0] = tf32r(wstage[ r      * WS_STRIDE + k0 + c    ]);
                a[b][1] = tf32r(wstage[(r + 8) * WS_STRIDE + k0 + c    ]);
                a[b][2] = tf32r(wstage[ r      * WS_STRIDE + k0 + c + 4]);
                a[b][3] = tf32r(wstage[(r + 8) * WS_STRIDE + k0 + c + 4]);
            }

            #pragma unroll
            for (int mt = 0; mt < 4; mt++) {
                uint32_t b0 = xs[(mt * 8 + g) * XS_STRIDE + k0 + c];
                uint32_t b1 = xs[(mt * 8 + g) * XS_STRIDE + k0 + 4 + c];
                MMA_TF32(acc[0][mt], a[0][0], a[0][1], a[0][2], a[0][3], b0, b1);
                MMA_TF32(acc[1][mt], a[1][0], a[1][1], a[1][2], a[1][3], b0, b1);
            }
        }

        __syncthreads();       // all warps done reading wstage + xs

        // refill this stage's buffer with tile kt+NSTAGE
        if (kt + NSTAGE < NKT) {
            const uint32_t dbase = smem_u32(wbuf + (kt & 1) * W_STAGE);
            const float*   gsrc  = W + (size_t)o_base * KDIM + (size_t)(kt + NSTAGE) * KTILE;
            #pragma unroll
            for (int i = 0; i < 8; i++) {
                int row = cprow0 + i * 8;
                cp_async16(dbase + (uint32_t)(row * WS_STRIDE + cpc4 * 4) * 4u,
                           gsrc + (size_t)row * KDIM + (size_t)cpc4 * 4);
            }
        }
        CP_COMMIT();
    }

    // ---- epilogue: reduce the 4 ks-quarters, then store ----
    CP_WAIT0();
    __syncthreads();                     // retire W buffer, reuse as reduction scratch
    // red[(q-1)][wrow][blk][mt][lane] as float4; 3*2*2*4*32*16B = 24,576 B
    float4* red = reinterpret_cast<float4*>(wbuf);
    if (q > 0) {
        #pragma unroll
        for (int b = 0; b < 2; b++)
            #pragma unroll
            for (int mt = 0; mt < 4; mt++)
                red[(((q - 1) * 2 + wrow) * 8 + b * 4 + mt) * 32 + lane] =
                    make_float4(acc[b][mt][0], acc[b][mt][1], acc[b][mt][2], acc[b][mt][3]);
    }
    __syncthreads();

    if (q == 0) {
        #pragma unroll
        for (int b = 0; b < 2; b++) {
            const int o0 = o_base + wrow * 32 + b * 16 + g;
            #pragma unroll
            for (int mt = 0; mt < 4; mt++) {
                float4 r = make_float4(acc[b][mt][0], acc[b][mt][1],
                                       acc[b][mt][2], acc[b][mt][3]);
                #pragma unroll
                for (int qq = 0; qq < 3; qq++) {
                    float4 v = red[((qq * 2 + wrow) * 8 + b * 4 + mt) * 32 + lane];
                    r.x += v.x; r.y += v.y; r.z += v.z; r.w += v.w;
                }
                const int m0 = mt * 8 + c * 2;
                // d0:(g,2c) d1:(g,2c+1) d2:(g+8,2c) d3:(g+8,2c+1); rows=o, cols=m
                out[(size_t)m0       * ODIM + o0    ] = r.x;
                out[(size_t)(m0 + 1) * ODIM + o0    ] = r.y;
                out[(size_t)m0       * ODIM + o0 + 8] = r.z;
                out[(size_t)(m0 + 1) * ODIM + o0 + 8] = r.w;
            }
        }
    }
}

extern "C" void kernel_launch(void* const* d_in, const int* in_sizes, int n_in,
                              void* d_out, int out_size) {
    const float* x = (const float*)d_in[0];
    const float* w = (const float*)d_in[1];
    const float* s = (const float*)d_in[2];
    float* out = (float*)d_out;

    const size_t smem_bytes = SMEM_FLOATS * sizeof(float);
    cudaFuncSetAttribute(linear_tf32_mma,
                         cudaFuncAttributeMaxDynamicSharedMemorySize, (int)smem_bytes);
    linear_tf32_mma<<<ODIM / OTILE, NTHREADS, smem_bytes>>>(x, w, s, out);
}